// round 17
// baseline (speedup 1.0000x reference)
#include <cuda_runtime.h>
#include <cstdint>

#define CC    512
#define KPW   256            // k-pair words per 512-k row
#define BSZ   8
#define HWSZ  16384
#define NTOT  131072
#define NH    65536          // NTOT/2 (packed-n width)

// Scratch (device globals; runtime allocation forbidden)
__device__ unsigned g_qk16a[(size_t)2 * KPW * NTOT];      // height Q,K packed [z2][cp][n]
__device__ unsigned g_qk16b[(size_t)2 * KPW * NTOT];
__device__ unsigned g_vpa  [(size_t)CC * NH];             // height V packed [c][np]
__device__ unsigned g_vpb  [(size_t)CC * NH];             // width  V packed
__device__ unsigned g_att16a[(size_t)KPW * NTOT];         // height attn out packed [cp][n]
__device__ unsigned g_att16b[(size_t)KPW * NTOT];
__device__ float    g_tmp  [(size_t)CC * NTOT];           // oh_t (xs-layout fp32)
__device__ float    g_ow   [(size_t)CC * NTOT];           // width out (xs-layout fp32)
__device__ unsigned g_xs16 [(size_t)BSZ * KPW * HWSZ];    // xs packed [b][cp][hw]
__device__ unsigned g_tmp16[(size_t)BSZ * KPW * HWSZ];    // T(xs) packed
__device__ unsigned g_wt16 [(size_t)8 * CC * KPW];        // weights packed [m][kp]

__device__ __forceinline__ unsigned pack_h2(float lo, float hi) {
    unsigned r;
    asm("cvt.rn.f16x2.f32 %0, %1, %2;" : "=r"(r) : "f"(hi), "f"(lo));
    return r;
}
#define CPA16(d, s) asm volatile("cp.async.cg.shared.global [%0], [%1], 16;" :: "r"(d), "l"(s))
#define MMA16(acc, a, b) asm volatile( \
    "mma.sync.aligned.m16n8k16.row.col.f32.f16.f16.f32 " \
    "{%0,%1,%2,%3}, {%4,%5,%6,%7}, {%8,%9}, {%0,%1,%2,%3};\n" \
    : "+f"(acc[0]), "+f"(acc[1]), "+f"(acc[2]), "+f"(acc[3]) \
    : "r"(a[0]), "r"(a[1]), "r"(a[2]), "r"(a[3]), "r"(b[0]), "r"(b[1]))

// ---------------- prep kernels ----------------
// All 8 weights in ONE launch (keeps ncu's -s 5 window on the real kernels).
__global__ void prep_w_all_kernel(
    const float* __restrict__ W0, const float* __restrict__ W1,
    const float* __restrict__ W2, const float* __restrict__ W3,
    const float* __restrict__ W4, const float* __restrict__ W5,
    const float* __restrict__ W6, const float* __restrict__ W7,
    unsigned* __restrict__ O)
{
    const float* Ws[8] = {W0, W1, W2, W3, W4, W5, W6, W7};
    int wsl = blockIdx.x >> 9;
    int idx = (blockIdx.x & 511) * 256 + threadIdx.x;      // 0..131071
    int m = idx >> 8, p = idx & 255;
    const float* W = Ws[wsl];
    O[(size_t)wsl * CC * KPW + idx] = pack_h2(W[m * CC + 2 * p], W[m * CC + 2 * p + 1]);
}
__global__ void pack_c_kernel(const float* __restrict__ xs, unsigned* __restrict__ o) {
    size_t u = (size_t)blockIdx.x * 256 + threadIdx.x;
    int bp = (int)(u >> 14), hw = (int)(u & 16383);
    int b = bp >> 8, p = bp & 255;
    const float* s = xs + ((size_t)(b * CC + 2 * p) << 14) + hw;
    o[u] = pack_h2(s[0], s[HWSZ]);
}
__global__ __launch_bounds__(256) void transpose_pack_kernel(
    const float* __restrict__ xs, unsigned* __restrict__ o)
{
    __shared__ float t0[32][33], t1[32][33];
    const int i0 = blockIdx.x * 32, j0 = blockIdx.y * 32;
    const int b = blockIdx.z >> 8, p = blockIdx.z & 255;
    const int tx = threadIdx.x, ty = threadIdx.y;
    const float* s0 = xs + ((size_t)(b * CC + 2 * p) << 14);
    const float* s1 = s0 + HWSZ;
#pragma unroll
    for (int r = 0; r < 4; r++) {
        t0[ty + 8 * r][tx] = s0[(i0 + ty + 8 * r) * 128 + j0 + tx];
        t1[ty + 8 * r][tx] = s1[(i0 + ty + 8 * r) * 128 + j0 + tx];
    }
    __syncthreads();
    unsigned* d = o + ((size_t)(b * KPW + p) << 14);
#pragma unroll
    for (int r = 0; r < 4; r++)
        d[(j0 + ty + 8 * r) * 128 + i0 + tx] =
            pack_h2(t0[tx][ty + 8 * r], t1[tx][ty + 8 * r]);
}
__global__ __launch_bounds__(256) void merge_kernel(
    const float* __restrict__ xs, const float* __restrict__ ohT,
    const float* __restrict__ ow, float* __restrict__ out)
{
    __shared__ float t[32][33];
    const int i0 = blockIdx.x * 32, j0 = blockIdx.y * 32;
    const long plane = (long)blockIdx.z * HWSZ;
    const int tx = threadIdx.x, ty = threadIdx.y;
#pragma unroll
    for (int r = 0; r < 4; r++)
        t[ty + 8 * r][tx] = ohT[plane + (long)(i0 + ty + 8 * r) * 128 + j0 + tx];
    __syncthreads();
#pragma unroll
    for (int r = 0; r < 4; r++) {
        long o = plane + (long)(j0 + ty + 8 * r) * 128 + i0 + tx;
        out[o] = xs[o] + ow[o] + t[tx][ty + 8 * r];
    }
}

// ---------------------------------------------------------------------------
// FP16 GEMM, packed gmem operands, 3-stage cp.async, L2-folded 1D grid.
// cmode 0 (proj): z<2 -> Cpk packed fp16 [z*256+cp][n] (shfl row-pairing);
//                 z==2 -> Vpk packed fp16 [c][np] (adjacent-n pairing, no shfl).
// cmode 1 (out):  Cf fp32 xs-layout.
// ---------------------------------------------------------------------------
#define A_PAD 20
#define B_PAD 136
#define A_WORDS (128 * A_PAD)
#define B_WORDS (16 * B_PAD)
#define STG_WORDS (A_WORDS + B_WORDS)
#define G16_STAGES 3
#define G16_SMEM (G16_STAGES * STG_WORDS * 4)   // 56832 B

__global__ __launch_bounds__(256) void tgemm16_kernel(
    const unsigned* __restrict__ A0, const unsigned* __restrict__ A1,
    const unsigned* __restrict__ A2,
    const unsigned* __restrict__ B,
    unsigned* __restrict__ Cpk, unsigned* __restrict__ Vpk,
    float* __restrict__ Cf, int bmode, int cmode, int inner)
{
    extern __shared__ unsigned gsm[];
    unsigned sbase;
    asm("{ .reg .u64 t; cvta.to.shared.u64 t, %1; cvt.u32.u64 %0, t; }"
        : "=r"(sbase) : "l"(gsm));

    const int t   = blockIdx.x;
    const int nix = t / inner;
    const int r   = t - nix * inner;
    const int z   = r >> 2;
    const int m0  = (r & 3) * 128;
    const int n0  = nix * 128;
    const unsigned* A = (z == 0) ? A0 : (z == 1) ? A1 : A2;

    const int tid  = threadIdx.x;
    const int lane = tid & 31;
    const int warp = tid >> 5;
    const int grp  = lane >> 2;
    const int qid  = lane & 3;
    const int mw   = (warp >> 2) * 64;
    const int nw   = (warp & 3) * 32;

    const unsigned* Bp;
    long ldb;
    if (bmode == 0) {
        int bb = n0 >> 14;
        Bp  = B + (((long)bb * KPW) << 14) + (n0 & (HWSZ - 1));
        ldb = HWSZ;
    } else {
        Bp  = B + n0;
        ldb = NTOT;
    }
    const int arow = tid >> 1, ah = (tid & 1) * 8;
    const unsigned* Agp = A + (long)(m0 + arow) * KPW + ah;
    const int brow = tid >> 4, bcw = (tid & 15) * 8;
    const unsigned* Bgp = Bp + (long)brow * ldb + bcw;
    const unsigned aoff = (unsigned)(arow * A_PAD + ah) * 4u;
    const unsigned boff = (unsigned)(A_WORDS + brow * B_PAD + bcw) * 4u;

    float acc[4][4][4];
#pragma unroll
    for (int mi = 0; mi < 4; mi++)
#pragma unroll
        for (int ni = 0; ni < 4; ni++)
#pragma unroll
            for (int q = 0; q < 4; q++) acc[mi][ni][q] = 0.0f;

    auto stage_load = [&](int st, int slab) {
        unsigned base = sbase + (unsigned)(st * STG_WORDS) * 4u;
        const unsigned* ag = Agp + slab * 16;
        CPA16(base + aoff,       ag);
        CPA16(base + aoff + 16u, ag + 4);
        const unsigned* bg = Bgp + (long)slab * 16 * ldb;
        CPA16(base + boff,       bg);
        CPA16(base + boff + 16u, bg + 4);
        asm volatile("cp.async.commit_group;");
    };

    stage_load(0, 0);
    stage_load(1, 1);
    stage_load(2, 2);

#pragma unroll 1
    for (int slab = 0; slab < 16; slab++) {
        const int st = slab % G16_STAGES;
        if      (slab <= 13) asm volatile("cp.async.wait_group 2;");
        else if (slab == 14) asm volatile("cp.async.wait_group 1;");
        else                 asm volatile("cp.async.wait_group 0;");
        __syncthreads();

        const unsigned* As = gsm + st * STG_WORDS;
        const unsigned* Bs = As + A_WORDS;

#pragma unroll
        for (int ks = 0; ks < 2; ks++) {
            const int kb = ks * 8;
            unsigned a[4][4], b[4][2];
#pragma unroll
            for (int mi = 0; mi < 4; mi++) {
                int mr = mw + mi * 16 + grp;
                a[mi][0] = As[mr * A_PAD + kb + qid];
                a[mi][1] = As[(mr + 8) * A_PAD + kb + qid];
                a[mi][2] = As[mr * A_PAD + kb + qid + 4];
                a[mi][3] = As[(mr + 8) * A_PAD + kb + qid + 4];
            }
#pragma unroll
            for (int ni = 0; ni < 4; ni++) {
                int nc = nw + ni * 8 + grp;
                b[ni][0] = Bs[(kb + qid) * B_PAD + nc];
                b[ni][1] = Bs[(kb + qid + 4) * B_PAD + nc];
            }
#pragma unroll
            for (int mi = 0; mi < 4; mi++)
#pragma unroll
                for (int ni = 0; ni < 4; ni++) MMA16(acc[mi][ni], a[mi], b[ni]);
        }
        __syncthreads();
        if (slab + G16_STAGES < 16) stage_load(st, slab + G16_STAGES);
    }

    const int cq = 2 * qid;
    if (cmode == 0) {
        if (z < 2) {
            // packed fp16 Q/K write: rows r0 (even grp) pair with r0+1 (lane+4)
            unsigned* Cp = Cpk + ((long)(z * 256 + (m0 >> 1))) * NTOT + n0;
#pragma unroll
            for (int mi = 0; mi < 4; mi++) {
#pragma unroll
                for (int ni = 0; ni < 4; ni++) {
                    float p0 = __shfl_down_sync(0xffffffffu, acc[mi][ni][0], 4);
                    float p1 = __shfl_down_sync(0xffffffffu, acc[mi][ni][1], 4);
                    float p2 = __shfl_down_sync(0xffffffffu, acc[mi][ni][2], 4);
                    float p3 = __shfl_down_sync(0xffffffffu, acc[mi][ni][3], 4);
                    if (!(grp & 1)) {
                        int rp  = (mw + mi * 16 + grp) >> 1;
                        int col = nw + ni * 8 + cq;
                        uint2 w0 = make_uint2(pack_h2(acc[mi][ni][0], p0),
                                              pack_h2(acc[mi][ni][1], p1));
                        uint2 w1 = make_uint2(pack_h2(acc[mi][ni][2], p2),
                                              pack_h2(acc[mi][ni][3], p3));
                        *(uint2*)(Cp + (long)rp * NTOT + col)       = w0;
                        *(uint2*)(Cp + (long)(rp + 4) * NTOT + col) = w1;
                    }
                }
            }
        } else {
            // V packed along n: acc[..][0,1] are adjacent cols -> direct pack
            unsigned* Cv = Vpk + (long)m0 * NH + (n0 >> 1);
#pragma unroll
            for (int mi = 0; mi < 4; mi++) {
                int r0 = mw + mi * 16 + grp;
#pragma unroll
                for (int ni = 0; ni < 4; ni++) {
                    int np = (nw + ni * 8 + cq) >> 1;
                    Cv[(long)r0 * NH + np] =
                        pack_h2(acc[mi][ni][0], acc[mi][ni][1]);
                    Cv[(long)(r0 + 8) * NH + np] =
                        pack_h2(acc[mi][ni][2], acc[mi][ni][3]);
                }
            }
        }
    } else {
        int bb = n0 >> 14;
        long off = (((long)bb * CC + m0) << 14) + (n0 & (HWSZ - 1));
        float* Cp = Cf + off;
#pragma unroll
        for (int mi = 0; mi < 4; mi++) {
            int r0 = mw + mi * 16 + grp;
#pragma unroll
            for (int ni = 0; ni < 4; ni++) {
                int col = nw + ni * 8 + cq;
                long o0 = (long)r0 * HWSZ + col;
                long o1 = (long)(r0 + 8) * HWSZ + col;
                *(float2*)(Cp + o0) = make_float2(acc[mi][ni][0], acc[mi][ni][1]);
                *(float2*)(Cp + o1) = make_float2(acc[mi][ni][2], acc[mi][ni][3]);
            }
        }
    }
}

// ---------------------------------------------------------------------------
// FP16 attention. Q,K packed [z2*256 cp][n]; V packed [c][np].
// Output packed fp16 att16 [cp][n].
// ---------------------------------------------------------------------------
#define AT_Q   0
#define AT_K   (32 * 136)
#define AT_V   (2 * 32 * 136)
#define AT_S   (AT_V + 64 * 68)
#define AT_O   (AT_S + 128 * 132)
#define AT_TOT (AT_O + 64 * 132)          // 38400 words = 153600 B

__global__ __launch_bounds__(256) void attn16_kernel(
    const unsigned* __restrict__ qk16, const unsigned* __restrict__ vpk,
    unsigned* __restrict__ att16)
{
    extern __shared__ unsigned smu[];
    unsigned* Qs = smu + AT_Q;
    unsigned* Ks = smu + AT_K;
    unsigned* Vs = smu + AT_V;
    float*    Sf = (float*)(smu + AT_S);
    float*    Os = (float*)(smu + AT_O);
    unsigned* Pp = smu;                    // overlays Qs+Ks after QK phase

    const int tid  = threadIdx.x;
    const int lane = tid & 31;
    const int warp = tid >> 5;
    const int grp  = lane >> 2;
    const int qid  = lane & 3;

    const int fix = blockIdx.x, head = blockIdx.y, b = blockIdx.z;
    const long bpos = (long)b * HWSZ + (long)fix * 128;
    const unsigned* Qg = qk16 + (long)(head * 32) * NTOT + bpos;
    const unsigned* Kg = qk16 + (long)(256 + head * 32) * NTOT + bpos;
    const unsigned* Vg = vpk + (long)(head * 64) * NH + (bpos >> 1);

#pragma unroll
    for (int it = 0; it < 16; it++) {
        int idx = it * 256 + tid;
        int dp = idx >> 7, s = idx & 127;
        Qs[dp * 136 + s] = Qg[(long)dp * NTOT + s];
        Ks[dp * 136 + s] = Kg[(long)dp * NTOT + s];
        int d = idx >> 6, jp = idx & 63;
        Vs[d * 68 + jp] = Vg[(long)d * NH + jp];
    }
    __syncthreads();

    // ---- S = Q^T K * 0.125 ; warps 4x2 of 32x64; 4 ks of kp8
    {
        const int mw = (warp >> 1) * 32, nw = (warp & 1) * 64;
        float acc[2][8][4];
#pragma unroll
        for (int mi = 0; mi < 2; mi++)
#pragma unroll
            for (int ni = 0; ni < 8; ni++)
#pragma unroll
                for (int q = 0; q < 4; q++) acc[mi][ni][q] = 0.f;
#pragma unroll
        for (int ks = 0; ks < 4; ks++) {
            const int kb = ks * 8;
            unsigned a[2][4], bf[8][2];
#pragma unroll
            for (int mi = 0; mi < 2; mi++) {
                int mr = mw + mi * 16 + grp;
                a[mi][0] = Qs[(kb + qid) * 136 + mr];
                a[mi][1] = Qs[(kb + qid) * 136 + mr + 8];
                a[mi][2] = Qs[(kb + qid + 4) * 136 + mr];
                a[mi][3] = Qs[(kb + qid + 4) * 136 + mr + 8];
            }
#pragma unroll
            for (int ni = 0; ni < 8; ni++) {
                int nc = nw + ni * 8 + grp;
                bf[ni][0] = Ks[(kb + qid) * 136 + nc];
                bf[ni][1] = Ks[(kb + qid + 4) * 136 + nc];
            }
#pragma unroll
            for (int mi = 0; mi < 2; mi++)
#pragma unroll
                for (int ni = 0; ni < 8; ni++) MMA16(acc[mi][ni], a[mi], bf[ni]);
        }
#pragma unroll
        for (int mi = 0; mi < 2; mi++) {
            int r0 = mw + mi * 16 + grp;
#pragma unroll
            for (int ni = 0; ni < 8; ni++) {
                int col = nw + ni * 8 + 2 * qid;
                Sf[r0 * 132 + col]           = acc[mi][ni][0] * 0.125f;
                Sf[r0 * 132 + col + 1]       = acc[mi][ni][1] * 0.125f;
                Sf[(r0 + 8) * 132 + col]     = acc[mi][ni][2] * 0.125f;
                Sf[(r0 + 8) * 132 + col + 1] = acc[mi][ni][3] * 0.125f;
            }
        }
    }
    __syncthreads();

    // ---- softmax rows -> packed P [i][jp] (overlay on Qs/Ks)
#pragma unroll
    for (int r = 0; r < 16; r++) {
        int row = warp + r * 8;
        float* rp = Sf + row * 132;
        float2 v01 = *(float2*)&rp[2 * lane];
        float2 v23 = *(float2*)&rp[2 * lane + 64];
        float mx = fmaxf(fmaxf(v01.x, v01.y), fmaxf(v23.x, v23.y));
#pragma unroll
        for (int o = 16; o > 0; o >>= 1) mx = fmaxf(mx, __shfl_xor_sync(~0u, mx, o));
        float e0 = __expf(v01.x - mx), e1 = __expf(v01.y - mx);
        float e2 = __expf(v23.x - mx), e3 = __expf(v23.y - mx);
        float s = e0 + e1 + e2 + e3;
#pragma unroll
        for (int o = 16; o > 0; o >>= 1) s += __shfl_xor_sync(~0u, s, o);
        float inv = 1.0f / s;
        Pp[row * 68 + lane]      = pack_h2(e0 * inv, e1 * inv);
        Pp[row * 68 + 32 + lane] = pack_h2(e2 * inv, e3 * inv);
    }
    __syncthreads();

    // ---- O^T[d][i] = sum_j V[d][j] P[i][j]; warps 2x4 of 32x32; 8 ks
    {
        const int mw = (warp >> 2) * 32, nw = (warp & 3) * 32;
        float acc[2][4][4];
#pragma unroll
        for (int mi = 0; mi < 2; mi++)
#pragma unroll
            for (int ni = 0; ni < 4; ni++)
#pragma unroll
                for (int q = 0; q < 4; q++) acc[mi][ni][q] = 0.f;
#pragma unroll
        for (int ks = 0; ks < 8; ks++) {
            const int kb = ks * 8;
            unsigned a[2][4], bf[4][2];
#pragma unroll
            for (int mi = 0; mi < 2; mi++) {
                int dr = mw + mi * 16 + grp;
                a[mi][0] = Vs[dr * 68 + kb + qid];
                a[mi][1] = Vs[(dr + 8) * 68 + kb + qid];
                a[mi][2] = Vs[dr * 68 + kb + qid + 4];
                a[mi][3] = Vs[(dr + 8) * 68 + kb + qid + 4];
            }
#pragma unroll
            for (int ni = 0; ni < 4; ni++) {
                int ir = nw + ni * 8 + grp;
                bf[ni][0] = Pp[ir * 68 + kb + qid];
                bf[ni][1] = Pp[ir * 68 + kb + qid + 4];
            }
#pragma unroll
            for (int mi = 0; mi < 2; mi++)
#pragma unroll
                for (int ni = 0; ni < 4; ni++) MMA16(acc[mi][ni], a[mi], bf[ni]);
        }
#pragma unroll
        for (int mi = 0; mi < 2; mi++) {
            int dr = mw + mi * 16 + grp;
#pragma unroll
            for (int ni = 0; ni < 4; ni++) {
                int ic = nw + ni * 8 + 2 * qid;
                *(float2*)&Os[dr * 132 + ic] =
                    make_float2(acc[mi][ni][0], acc[mi][ni][1]);
                *(float2*)&Os[(dr + 8) * 132 + ic] =
                    make_float2(acc[mi][ni][2], acc[mi][ni][3]);
            }
        }
    }
    __syncthreads();

#pragma unroll
    for (int it = 0; it < 16; it++) {
        int idx = it * 256 + tid;
        int dp = idx >> 7, i = idx & 127;
        att16[(long)(head * 32 + dp) * NTOT + bpos + i] =
            pack_h2(Os[2 * dp * 132 + i], Os[(2 * dp + 1) * 132 + i]);
    }
}

// ---------------------------------------------------------------------------
struct StreamSet {
    cudaStream_t s2;
    cudaEvent_t fork, join;
    StreamSet() {
        cudaStreamCreateWithFlags(&s2, cudaStreamNonBlocking);
        cudaEventCreateWithFlags(&fork, cudaEventDisableTiming);
        cudaEventCreateWithFlags(&join, cudaEventDisableTiming);
    }
};
static StreamSet g_ss;

extern "C" void kernel_launch(void* const* d_in, const int* in_sizes, int n_in,
                              void* d_out, int out_size)
{
    const float* xs = (const float*)d_in[0];
    float* out = (float*)d_out;

    unsigned *qk16a, *qk16b, *vpa, *vpb, *att16a, *att16b, *xs16, *tmp16, *wt16;
    float *tmp, *ow;
    cudaGetSymbolAddress((void**)&qk16a,  g_qk16a);
    cudaGetSymbolAddress((void**)&qk16b,  g_qk16b);
    cudaGetSymbolAddress((void**)&vpa,    g_vpa);
    cudaGetSymbolAddress((void**)&vpb,    g_vpb);
    cudaGetSymbolAddress((void**)&att16a, g_att16a);
    cudaGetSymbolAddress((void**)&att16b, g_att16b);
    cudaGetSymbolAddress((void**)&tmp,    g_tmp);
    cudaGetSymbolAddress((void**)&ow,     g_ow);
    cudaGetSymbolAddress((void**)&xs16,   g_xs16);
    cudaGetSymbolAddress((void**)&tmp16,  g_tmp16);
    cudaGetSymbolAddress((void**)&wt16,   g_wt16);

    cudaFuncSetAttribute(attn16_kernel,
                         cudaFuncAttributeMaxDynamicSharedMemorySize, AT_TOT * 4);
    cudaFuncSetAttribute(tgemm16_kernel,
                         cudaFuncAttributeMaxDynamicSharedMemorySize, G16_SMEM);

    prep_w_all_kernel<<<8 * 512, 256>>>(
        (const float*)d_in[1], (const float*)d_in[2], (const float*)d_in[3],
        (const float*)d_in[4], (const float*)d_in[5], (const float*)d_in[6],
        (const float*)d_in[7], (const float*)d_in[8], wt16);
    pack_c_kernel<<<(int)(((size_t)BSZ * KPW * HWSZ) / 256), 256>>>(xs, xs16);

    cudaEventRecord(g_ss.fork, 0);
    cudaStreamWaitEvent(g_ss.s2, g_ss.fork, 0);

    dim3 gproj(1024 * 12, 1, 1);
    dim3 gout (1024 * 4, 1, 1);
    dim3 gattn(128, 8, BSZ);
    dim3 gtr(4, 4, BSZ * KPW);
    dim3 gtrm(4, 4, BSZ * CC);
    dim3 btr(32, 8);

    // ---- height branch (stream 0): seq = h via transposed packed planes ----
    transpose_pack_kernel<<<gtr, btr>>>(xs, tmp16);
    tgemm16_kernel<<<gproj, 256, G16_SMEM>>>(wt16 + 0ull * CC * KPW,
                                             wt16 + 1ull * CC * KPW,
                                             wt16 + 2ull * CC * KPW,
                                             tmp16, qk16a, vpa, nullptr, 0, 0, 12);
    attn16_kernel<<<gattn, 256, AT_TOT * 4>>>(qk16a, vpa, att16a);
    tgemm16_kernel<<<gout, 256, G16_SMEM>>>(wt16 + 3ull * CC * KPW,
                                            wt16 + 3ull * CC * KPW,
                                            wt16 + 3ull * CC * KPW,
                                            att16a, nullptr, nullptr, tmp, 1, 1, 4);

    // ---- width branch (stream s2): seq = w natively ----
    tgemm16_kernel<<<gproj, 256, G16_SMEM, g_ss.s2>>>(wt16 + 4ull * CC * KPW,
                                                      wt16 + 5ull * CC * KPW,
                                                      wt16 + 6ull * CC * KPW,
                                                      xs16, qk16b, vpb, nullptr, 0, 0, 12);
    attn16_kernel<<<gattn, 256, AT_TOT * 4, g_ss.s2>>>(qk16b, vpb, att16b);
    tgemm16_kernel<<<gout, 256, G16_SMEM, g_ss.s2>>>(wt16 + 7ull * CC * KPW,
                                                     wt16 + 7ull * CC * KPW,
                                                     wt16 + 7ull * CC * KPW,
                                                     att16b, nullptr, nullptr, ow, 1, 1, 4);

    // join + merge: out = xs + T(oh_t) + ow
    cudaEventRecord(g_ss.join, g_ss.s2);
    cudaStreamWaitEvent(0, g_ss.join, 0);
    merge_kernel<<<gtrm, btr>>>(xs, tmp, ow, out);
}